// round 1
// baseline (speedup 1.0000x reference)
#include <cuda_runtime.h>
#include <cstdint>

// Problem constants (fixed by setup_inputs)
#define B_  2
#define V_  4
#define N_  2048
#define F_  128
#define E_  32768
#define ET_ (E_ + N_)      // 34816 edges incl self-loops
#define O_  512
#define TO_ 1024           // C row = [C1 | C2]

// ---------------- scratch (device globals; no runtime alloc) ----------------
__device__ float g_C[B_ * V_ * N_ * TO_];   // 64 MB: C[b][v][n][0:512]=x@W1, [512:1024]=x@W2
__device__ float g_Wp[F_ * TO_];            // packed [W1 | W2] (128 x 1024)
__device__ float g_sa[B_ * 16 * N_];        // salpha per (b, pair=g*4+hv, n)
__device__ float g_sb[B_ * 16 * N_];
__device__ float g_w[B_ * ET_ * 16];        // softmax weights, [b][edge][pair]
__device__ int   g_cnt[N_];
__device__ int   g_off[N_ + 1];
__device__ int   g_fill[N_];
__device__ int   g_srcs[ET_];
__device__ int   g_eids[ET_];

// sign-flip predicate: features {0,2} flip when r&1, {1,3} flip when r&2
__device__ __forceinline__ bool flip_jr(int j, int r) {
    return ((j & 1) == 0) ? ((r & 1) != 0) : ((r & 2) != 0);
}

__device__ __forceinline__ float4 f4z() { return make_float4(0.f, 0.f, 0.f, 0.f); }
__device__ __forceinline__ void f4fma(float4& acc, float s, const float4& a) {
    acc.x += s * a.x; acc.y += s * a.y; acc.z += s * a.z; acc.w += s * a.w;
}
__device__ __forceinline__ void f4add(float4& acc, const float4& a) {
    acc.x += a.x; acc.y += a.y; acc.z += a.z; acc.w += a.w;
}

// ---------------- K0: pack W -> Wp[k][j] = (j<512 ? W1[k][j] : W2[k][j-512]) --
__global__ void k_pack(const float* __restrict__ W) {
    int i = blockIdx.x * blockDim.x + threadIdx.x;
    if (i >= F_ * TO_) return;
    int k = i / TO_, j = i % TO_;
    g_Wp[i] = (j < O_) ? W[k * O_ + j] : W[(F_ + k) * O_ + (j - O_)];
}

// ---------------- K1: C[bv] = x[bv](2048x128) @ Wp(128x1024) ----------------
// BM=128, BN=64, BK=32, 256 threads, 8x4 thread tiles.
__global__ __launch_bounds__(256) void k_gemm(const float* __restrict__ x) {
    __shared__ float As[128][36];  // [m][k], pad 4 (16B-aligned rows, spreads banks)
    __shared__ float Bs[32][64];   // [k][n]
    const int bv = blockIdx.z;
    const int m0 = blockIdx.y * 128;
    const int n0 = blockIdx.x * 64;
    const int t  = threadIdx.x;
    const int tm = t >> 4;       // 0..15  (8 rows each)
    const int tn = t & 15;       // 0..15  (4 cols each)

    float4 acc[8];
#pragma unroll
    for (int i = 0; i < 8; i++) acc[i] = f4z();

    const float* xA = x + (size_t)bv * N_ * F_ + (size_t)m0 * F_;

    for (int kc = 0; kc < 4; kc++) {
        // load A tile: 128x32 floats
#pragma unroll
        for (int it = 0; it < 4; it++) {
            int f = t + it * 256;
            int m = f >> 3;
            int kq = (f & 7) * 4;
            float4 v = *(const float4*)&xA[m * F_ + kc * 32 + kq];
            *(float4*)&As[m][kq] = v;
        }
        // load B tile: 32x64 floats
#pragma unroll
        for (int it = 0; it < 2; it++) {
            int f = t + it * 256;
            int k = f >> 4;
            int nq = (f & 15) * 4;
            float4 v = *(const float4*)&g_Wp[(kc * 32 + k) * TO_ + n0 + nq];
            *(float4*)&Bs[k][nq] = v;
        }
        __syncthreads();
#pragma unroll
        for (int kk = 0; kk < 32; kk++) {
            float4 b4 = *(float4*)&Bs[kk][tn * 4];
            float a[8];
#pragma unroll
            for (int i = 0; i < 8; i++) a[i] = As[tm * 8 + i][kk];
#pragma unroll
            for (int i = 0; i < 8; i++) f4fma(acc[i], a[i], b4);
        }
        __syncthreads();
    }

    float* Cp = g_C + (size_t)bv * N_ * TO_;
#pragma unroll
    for (int i = 0; i < 8; i++)
        *(float4*)&Cp[(size_t)(m0 + tm * 8 + i) * TO_ + n0 + tn * 4] = acc[i];
}

// ---------------- K2: CSR build (count / scan / fill) -----------------------
__global__ void k_zero() {
    int i = blockIdx.x * blockDim.x + threadIdx.x;
    if (i < N_) g_cnt[i] = 0;
}
__global__ void k_count(const int* __restrict__ ei) {
    int e = blockIdx.x * blockDim.x + threadIdx.x;
    if (e >= ET_) return;
    int d = (e < E_) ? ei[E_ + e] : e - E_;
    atomicAdd(&g_cnt[d], 1);
}
__global__ __launch_bounds__(1024) void k_scan() {
    __shared__ int sh[N_];
    int t = threadIdx.x;
    sh[t] = g_cnt[t];
    sh[t + 1024] = g_cnt[t + 1024];
    __syncthreads();
    for (int d = 1; d < N_; d <<= 1) {
        int i0 = t, i1 = t + 1024;
        int v0 = (i0 >= d) ? sh[i0 - d] : 0;
        int v1 = (i1 >= d) ? sh[i1 - d] : 0;
        __syncthreads();
        sh[i0] += v0;
        sh[i1] += v1;
        __syncthreads();
    }
    g_off[t + 1] = sh[t];
    g_off[t + 1025] = sh[t + 1024];
    g_fill[t] = (t == 0) ? 0 : sh[t - 1];
    g_fill[t + 1024] = sh[t + 1023];
    if (t == 0) g_off[0] = 0;
}
__global__ void k_fill(const int* __restrict__ ei) {
    int e = blockIdx.x * blockDim.x + threadIdx.x;
    if (e >= ET_) return;
    int s = (e < E_) ? ei[e] : e - E_;
    int d = (e < E_) ? ei[E_ + e] : e - E_;
    int slot = atomicAdd(&g_fill[d], 1);
    g_srcs[slot] = s;
    g_eids[slot] = e;
}

// ---------------- K3: salpha/sbeta per (b, n, 16 pairs) ---------------------
// block = (n, b), 128 threads, o0 = t*4 covers 512 outputs
__global__ __launch_bounds__(128) void k_sab(const float* __restrict__ x,
                                             const float* __restrict__ att) {
    const int n = blockIdx.x, b = blockIdx.y;
    const int t = threadIdx.x;
    const int o0 = t * 4;

    __shared__ float sx[V_][4];
    if (t < 16) sx[t >> 2][t & 3] = x[((size_t)(b * V_ + (t >> 2)) * N_ + n) * F_ + (t & 3)];
    __syncthreads();

    float4 c1[4], c2[4], w1[4], w2[4];
#pragma unroll
    for (int v = 0; v < 4; v++) {
        const float* cp = &g_C[((size_t)(b * V_ + v) * N_ + n) * TO_];
        c1[v] = *(const float4*)&cp[o0];
        c2[v] = *(const float4*)&cp[512 + o0];
    }
#pragma unroll
    for (int j = 0; j < 4; j++) {
        w1[j] = *(const float4*)&g_Wp[j * TO_ + o0];
        w2[j] = *(const float4*)&g_Wp[j * TO_ + 512 + o0];
    }
    float4 a1 = *(const float4*)&att[o0];
    float4 a2 = *(const float4*)&att[512 + o0];

    float red[32];
#pragma unroll
    for (int g = 0; g < 4; g++) {
#pragma unroll
        for (int hv = 0; hv < 4; hv++) {
            const int u = g ^ hv;
            float4 h = c1[hv];
            f4add(h, c2[u]);
#pragma unroll
            for (int j = 0; j < 4; j++) {
                if (flip_jr(j, u))  f4fma(h, -2.f * sx[hv][j], w1[j]);
                if (flip_jr(j, hv)) f4fma(h, -2.f * sx[u][j],  w2[j]);
            }
            float4 lh;
            lh.x = h.x > 0.f ? h.x : 0.2f * h.x;
            lh.y = h.y > 0.f ? h.y : 0.2f * h.y;
            lh.z = h.z > 0.f ? h.z : 0.2f * h.z;
            lh.w = h.w > 0.f ? h.w : 0.2f * h.w;
            red[g * 4 + hv]      = a1.x * lh.x + a1.y * lh.y + a1.z * lh.z + a1.w * lh.w;
            red[16 + g * 4 + hv] = a2.x * lh.x + a2.y * lh.y + a2.z * lh.z + a2.w * lh.w;
        }
    }
    // block-reduce 32 values over 128 threads
#pragma unroll
    for (int o2 = 16; o2; o2 >>= 1)
#pragma unroll
        for (int i = 0; i < 32; i++) red[i] += __shfl_xor_sync(0xffffffffu, red[i], o2);
    __shared__ float sred[4][32];
    int warp = t >> 5, lane = t & 31;
    if (lane == 0) {
#pragma unroll
        for (int i = 0; i < 32; i++) sred[warp][i] = red[i];
    }
    __syncthreads();
    if (t < 32) {
        float v = sred[0][t] + sred[1][t] + sred[2][t] + sred[3][t];
        if (t < 16) g_sa[(size_t)(b * 16 + t) * N_ + n] = v;
        else        g_sb[(size_t)(b * 16 + (t - 16)) * N_ + n] = v;
    }
}

// ---------------- K4: global softmax per (b, pair) over all edges -----------
__global__ __launch_bounds__(512) void k_soft(const int* __restrict__ ei) {
    const int b = blockIdx.x >> 4, p = blockIdx.x & 15;
    const float* sa = &g_sa[(size_t)(b * 16 + p) * N_];
    const float* sb = &g_sb[(size_t)(b * 16 + p) * N_];
    __shared__ float red[512];
    const int t = threadIdx.x;

    float lm = -1e30f;
    for (int e = t; e < ET_; e += 512) {
        int s = (e < E_) ? ei[e] : e - E_;
        int d = (e < E_) ? ei[E_ + e] : e - E_;
        lm = fmaxf(lm, sa[s] + sb[d]);
    }
    red[t] = lm;
    __syncthreads();
    for (int o2 = 256; o2; o2 >>= 1) {
        if (t < o2) red[t] = fmaxf(red[t], red[t + o2]);
        __syncthreads();
    }
    const float mx = red[0];
    __syncthreads();

    float ls = 0.f;
    for (int e = t; e < ET_; e += 512) {
        int s = (e < E_) ? ei[e] : e - E_;
        int d = (e < E_) ? ei[E_ + e] : e - E_;
        ls += __expf(sa[s] + sb[d] - mx);
    }
    red[t] = ls;
    __syncthreads();
    for (int o2 = 256; o2; o2 >>= 1) {
        if (t < o2) red[t] += red[t + o2];
        __syncthreads();
    }
    const float inv = 1.f / red[0];

    for (int e = t; e < ET_; e += 512) {
        int s = (e < E_) ? ei[e] : e - E_;
        int d = (e < E_) ? ei[E_ + e] : e - E_;
        g_w[(size_t)(b * ET_ + e) * 16 + p] = __expf(sa[s] + sb[d] - mx) * inv;
    }
}

// ---------------- K5: edge-weighted gather/accumulate + epilogue ------------
// block = (dst n, b), 128 threads, o0 = t*4
__global__ __launch_bounds__(128) void k_edge(const float* __restrict__ x,
                                              const float* __restrict__ bias,
                                              float* __restrict__ out) {
    const int n = blockIdx.x, b = blockIdx.y;
    const int t = threadIdx.x;
    const int o0 = t * 4;
    const int beg = g_off[n], end = g_off[n + 1];

    float4 acc[4];
#pragma unroll
    for (int g = 0; g < 4; g++) acc[g] = f4z();

    for (int idx = beg; idx < end; idx++) {
        const int s = g_srcs[idx];
        const int eid = g_eids[idx];
        const float4* wp = (const float4*)&g_w[(size_t)(b * ET_ + eid) * 16];
        float4 w0 = wp[0], w1v = wp[1], w2v = wp[2], w3v = wp[3];
        float wv[16] = {w0.x, w0.y, w0.z, w0.w, w1v.x, w1v.y, w1v.z, w1v.w,
                        w2v.x, w2v.y, w2v.z, w2v.w, w3v.x, w3v.y, w3v.z, w3v.w};
        float4 c1[4], c2[4];
#pragma unroll
        for (int v = 0; v < 4; v++) {
            const float* cp = &g_C[((size_t)(b * V_ + v) * N_ + s) * TO_];
            c1[v] = *(const float4*)&cp[o0];
            c2[v] = *(const float4*)&cp[512 + o0];
        }
#pragma unroll
        for (int g = 0; g < 4; g++) {
#pragma unroll
            for (int v = 0; v < 4; v++) {
                f4fma(acc[g], wv[g * 4 + v], c1[v]);
                f4fma(acc[g], wv[g * 4 + (g ^ v)], c2[v]);
            }
        }
    }

    // rank-4 correction scalars: 4g x (4 for W1 rows + 4 for W2 rows)
    float cr[32];
#pragma unroll
    for (int i = 0; i < 32; i++) cr[i] = 0.f;
    for (int idx = beg + t; idx < end; idx += 128) {
        const int s = g_srcs[idx];
        const int eid = g_eids[idx];
        const float4* wp = (const float4*)&g_w[(size_t)(b * ET_ + eid) * 16];
        float4 w0 = wp[0], w1v = wp[1], w2v = wp[2], w3v = wp[3];
        float wv[16] = {w0.x, w0.y, w0.z, w0.w, w1v.x, w1v.y, w1v.z, w1v.w,
                        w2v.x, w2v.y, w2v.z, w2v.w, w3v.x, w3v.y, w3v.z, w3v.w};
        float xb[4][4];
#pragma unroll
        for (int v = 0; v < 4; v++) {
            float4 tv = *(const float4*)&x[((size_t)(b * V_ + v) * N_ + s) * F_];
            xb[v][0] = tv.x; xb[v][1] = tv.y; xb[v][2] = tv.z; xb[v][3] = tv.w;
        }
#pragma unroll
        for (int g = 0; g < 4; g++) {
#pragma unroll
            for (int hv = 0; hv < 4; hv++) {
                const float wgh = wv[g * 4 + hv];
                const int u = g ^ hv;
#pragma unroll
                for (int j = 0; j < 4; j++) {
                    if (flip_jr(j, u))  cr[g * 8 + j]     += wgh * (-2.f) * xb[hv][j];
                    if (flip_jr(j, hv)) cr[g * 8 + 4 + j] += wgh * (-2.f) * xb[u][j];
                }
            }
        }
    }
#pragma unroll
    for (int o2 = 16; o2; o2 >>= 1)
#pragma unroll
        for (int i = 0; i < 32; i++) cr[i] += __shfl_xor_sync(0xffffffffu, cr[i], o2);

    __shared__ float sred[4][32];
    __shared__ float fc[32];
    const int warp = t >> 5, lane = t & 31;
    if (lane == 0) {
#pragma unroll
        for (int i = 0; i < 32; i++) sred[warp][i] = cr[i];
    }
    __syncthreads();
    if (t < 32) fc[t] = sred[0][t] + sred[1][t] + sred[2][t] + sred[3][t];
    __syncthreads();

    float4 w1r[4], w2r[4];
#pragma unroll
    for (int j = 0; j < 4; j++) {
        w1r[j] = *(const float4*)&g_Wp[j * TO_ + o0];
        w2r[j] = *(const float4*)&g_Wp[j * TO_ + 512 + o0];
    }
    float4 bb = *(const float4*)&bias[o0];
#pragma unroll
    for (int g = 0; g < 4; g++) {
        float4 r = acc[g];
#pragma unroll
        for (int j = 0; j < 4; j++) {
            f4fma(r, fc[g * 8 + j], w1r[j]);
            f4fma(r, fc[g * 8 + 4 + j], w2r[j]);
        }
        float4 o4;
        o4.x = 0.25f * r.x + bb.x;
        o4.y = 0.25f * r.y + bb.y;
        o4.z = 0.25f * r.z + bb.z;
        o4.w = 0.25f * r.w + bb.w;
        *(float4*)&out[((size_t)(b * V_ + g) * N_ + n) * O_ + o0] = o4;
    }
}

// ---------------- launch ----------------------------------------------------
extern "C" void kernel_launch(void* const* d_in, const int* in_sizes, int n_in,
                              void* d_out, int out_size) {
    const float* x    = (const float*)d_in[0];
    const int*   ei   = (const int*)d_in[1];
    const float* W    = (const float*)d_in[2];
    const float* att  = (const float*)d_in[3];
    const float* bias = (const float*)d_in[4];
    float* out = (float*)d_out;

    k_pack<<<(F_ * TO_ + 255) / 256, 256>>>(W);
    k_gemm<<<dim3(16, 16, 8), 256>>>(x);
    k_zero<<<(N_ + 255) / 256, 256>>>();
    k_count<<<(ET_ + 255) / 256, 256>>>(ei);
    k_scan<<<1, 1024>>>();
    k_fill<<<(ET_ + 255) / 256, 256>>>(ei);
    k_sab<<<dim3(N_, B_), 128>>>(x, att);
    k_soft<<<32, 512>>>(ei);
    k_edge<<<dim3(N_, B_), 128>>>(x, bias, out);
}

// round 2
// speedup vs baseline: 1.0287x; 1.0287x over previous
#include <cuda_runtime.h>
#include <cuda_fp16.h>
#include <cstdint>

// Problem constants (fixed by setup_inputs)
#define B_  2
#define V_  4
#define N_  2048
#define F_  128
#define E_  32768
#define ET_ (E_ + N_)      // 34816 edges incl self-loops
#define O_  512
#define TO_ 1024           // C row = [C1 | C2]

// ---------------- scratch (device globals; no runtime alloc) ----------------
__device__ float  g_C [B_ * V_ * N_ * TO_];  // 64 MB fp32 (for exact scores)
__device__ __half g_Ch[B_ * V_ * N_ * TO_];  // 32 MB fp16 shadow (edge pass)
__device__ float  g_Wp[F_ * TO_];            // packed [W1 | W2] (128 x 1024)
__device__ float  g_sa[B_ * 16 * N_];
__device__ float  g_sb[B_ * 16 * N_];
__device__ float  g_w [B_ * ET_ * 16];       // softmax weights [b][edge][pair]
__device__ int    g_cnt[N_];
__device__ int    g_off[N_ + 1];
__device__ int    g_fill[N_];
__device__ int    g_srcs[ET_];
__device__ int    g_eids[ET_];

// sign-flip predicate: features {0,2} flip when r&1, {1,3} flip when r&2
__device__ __forceinline__ bool flip_jr(int j, int r) {
    return ((j & 1) == 0) ? ((r & 1) != 0) : ((r & 2) != 0);
}
__device__ __forceinline__ float4 f4z() { return make_float4(0.f, 0.f, 0.f, 0.f); }
__device__ __forceinline__ void f4fma(float4& acc, float s, const float4& a) {
    acc.x += s * a.x; acc.y += s * a.y; acc.z += s * a.z; acc.w += s * a.w;
}
__device__ __forceinline__ void f4add(float4& acc, const float4& a) {
    acc.x += a.x; acc.y += a.y; acc.z += a.z; acc.w += a.w;
}

// ---------------- K0: pack W + zero counters --------------------------------
__global__ void k_prep(const float* __restrict__ W) {
    int i = blockIdx.x * blockDim.x + threadIdx.x;
    if (i < N_) g_cnt[i] = 0;
    if (i >= F_ * TO_) return;
    int k = i / TO_, j = i % TO_;
    g_Wp[i] = (j < O_) ? W[k * O_ + j] : W[(F_ + k) * O_ + (j - O_)];
}

// ---------------- K1: C[bv] = x[bv](2048x128) @ Wp(128x1024) ----------------
// BM=128, BN=128, BK=16, 256 threads, 8x8 microtile, reg-staged double buffer.
__global__ __launch_bounds__(256, 2) void k_gemm(const float* __restrict__ x) {
    __shared__ float As[2][16][132];   // [k][m], padded
    __shared__ float Bs[2][16][128];   // [k][n]
    const int bv = blockIdx.z;
    const int m0 = blockIdx.y * 128;
    const int n0 = blockIdx.x * 128;
    const int t  = threadIdx.x;
    const int tm = t >> 4;       // 0..15
    const int tn = t & 15;       // 0..15

    const float* xA = x + ((size_t)bv * N_ + m0) * F_;

    // per-thread load coordinates (fixed)
    const int fA0 = t * 2,     mA0 = fA0 >> 2, kqA0 = (fA0 & 3) * 4;
    const int fA1 = t * 2 + 1, mA1 = fA1 >> 2, kqA1 = (fA1 & 3) * 4;
    const int kB0 = t >> 5,    nqB = (t & 31) * 4;
    const int kB1 = kB0 + 8;

    float4 ra0, ra1, rb0, rb1;

    // prologue: ldg kc=0, sts buf0
    ra0 = *(const float4*)&xA[mA0 * F_ + 0 + kqA0];
    ra1 = *(const float4*)&xA[mA1 * F_ + 0 + kqA1];
    rb0 = *(const float4*)&g_Wp[(0 + kB0) * TO_ + n0 + nqB];
    rb1 = *(const float4*)&g_Wp[(0 + kB1) * TO_ + n0 + nqB];
    As[0][kqA0 + 0][mA0] = ra0.x; As[0][kqA0 + 1][mA0] = ra0.y;
    As[0][kqA0 + 2][mA0] = ra0.z; As[0][kqA0 + 3][mA0] = ra0.w;
    As[0][kqA1 + 0][mA1] = ra1.x; As[0][kqA1 + 1][mA1] = ra1.y;
    As[0][kqA1 + 2][mA1] = ra1.z; As[0][kqA1 + 3][mA1] = ra1.w;
    *(float4*)&Bs[0][kB0][nqB] = rb0;
    *(float4*)&Bs[0][kB1][nqB] = rb1;
    __syncthreads();

    float acc[8][8];
#pragma unroll
    for (int i = 0; i < 8; i++)
#pragma unroll
        for (int j = 0; j < 8; j++) acc[i][j] = 0.f;

    int buf = 0;
    for (int kc = 0; kc < 8; kc++) {
        if (kc < 7) {
            const int k16 = (kc + 1) * 16;
            ra0 = *(const float4*)&xA[mA0 * F_ + k16 + kqA0];
            ra1 = *(const float4*)&xA[mA1 * F_ + k16 + kqA1];
            rb0 = *(const float4*)&g_Wp[(k16 + kB0) * TO_ + n0 + nqB];
            rb1 = *(const float4*)&g_Wp[(k16 + kB1) * TO_ + n0 + nqB];
        }
#pragma unroll
        for (int kk = 0; kk < 16; kk++) {
            float4 aA = *(const float4*)&As[buf][kk][tm * 8];
            float4 aB = *(const float4*)&As[buf][kk][tm * 8 + 4];
            float4 bA = *(const float4*)&Bs[buf][kk][tn * 4];
            float4 bB = *(const float4*)&Bs[buf][kk][64 + tn * 4];
            float a[8] = {aA.x, aA.y, aA.z, aA.w, aB.x, aB.y, aB.z, aB.w};
            float bb[8] = {bA.x, bA.y, bA.z, bA.w, bB.x, bB.y, bB.z, bB.w};
#pragma unroll
            for (int i = 0; i < 8; i++)
#pragma unroll
                for (int j = 0; j < 8; j++)
                    acc[i][j] += a[i] * bb[j];
        }
        if (kc < 7) {
            const int nb = buf ^ 1;
            As[nb][kqA0 + 0][mA0] = ra0.x; As[nb][kqA0 + 1][mA0] = ra0.y;
            As[nb][kqA0 + 2][mA0] = ra0.z; As[nb][kqA0 + 3][mA0] = ra0.w;
            As[nb][kqA1 + 0][mA1] = ra1.x; As[nb][kqA1 + 1][mA1] = ra1.y;
            As[nb][kqA1 + 2][mA1] = ra1.z; As[nb][kqA1 + 3][mA1] = ra1.w;
            *(float4*)&Bs[nb][kB0][nqB] = rb0;
            *(float4*)&Bs[nb][kB1][nqB] = rb1;
        }
        __syncthreads();
        buf ^= 1;
    }

#pragma unroll
    for (int i = 0; i < 8; i++) {
        const int row = m0 + tm * 8 + i;
        float*  Cp = &g_C [((size_t)bv * N_ + row) * TO_];
        __half* Hp = &g_Ch[((size_t)bv * N_ + row) * TO_];
        float4 v0 = make_float4(acc[i][0], acc[i][1], acc[i][2], acc[i][3]);
        float4 v1 = make_float4(acc[i][4], acc[i][5], acc[i][6], acc[i][7]);
        const int c0 = n0 + tn * 4, c1 = n0 + 64 + tn * 4;
        *(float4*)&Cp[c0] = v0;
        *(float4*)&Cp[c1] = v1;
        *(__half2*)&Hp[c0]     = __floats2half2_rn(v0.x, v0.y);
        *(__half2*)&Hp[c0 + 2] = __floats2half2_rn(v0.z, v0.w);
        *(__half2*)&Hp[c1]     = __floats2half2_rn(v1.x, v1.y);
        *(__half2*)&Hp[c1 + 2] = __floats2half2_rn(v1.z, v1.w);
    }
}

// ---------------- K2: CSR build (count / scan / fill) -----------------------
__global__ void k_count(const int* __restrict__ ei) {
    int e = blockIdx.x * blockDim.x + threadIdx.x;
    if (e >= ET_) return;
    int d = (e < E_) ? ei[E_ + e] : e - E_;
    atomicAdd(&g_cnt[d], 1);
}
__global__ __launch_bounds__(1024) void k_scan() {
    __shared__ int sh[N_];
    int t = threadIdx.x;
    sh[t] = g_cnt[t];
    sh[t + 1024] = g_cnt[t + 1024];
    __syncthreads();
    for (int d = 1; d < N_; d <<= 1) {
        int i0 = t, i1 = t + 1024;
        int v0 = (i0 >= d) ? sh[i0 - d] : 0;
        int v1 = (i1 >= d) ? sh[i1 - d] : 0;
        __syncthreads();
        sh[i0] += v0;
        sh[i1] += v1;
        __syncthreads();
    }
    g_off[t + 1] = sh[t];
    g_off[t + 1025] = sh[t + 1024];
    g_fill[t] = (t == 0) ? 0 : sh[t - 1];
    g_fill[t + 1024] = sh[t + 1023];
    if (t == 0) g_off[0] = 0;
}
__global__ void k_fill(const int* __restrict__ ei) {
    int e = blockIdx.x * blockDim.x + threadIdx.x;
    if (e >= ET_) return;
    int s = (e < E_) ? ei[e] : e - E_;
    int d = (e < E_) ? ei[E_ + e] : e - E_;
    int slot = atomicAdd(&g_fill[d], 1);
    g_srcs[slot] = s;
    g_eids[slot] = e;
}

// ---------------- K3: salpha/sbeta per (b, n, 16 pairs) ---------------------
__global__ __launch_bounds__(128) void k_sab(const float* __restrict__ x,
                                             const float* __restrict__ att) {
    const int n = blockIdx.x, b = blockIdx.y;
    const int t = threadIdx.x;
    const int o0 = t * 4;

    __shared__ float sx[V_][4];
    if (t < 16) sx[t >> 2][t & 3] = x[((size_t)(b * V_ + (t >> 2)) * N_ + n) * F_ + (t & 3)];
    __syncthreads();

    float4 c1[4], c2[4], w1[4], w2[4];
#pragma unroll
    for (int v = 0; v < 4; v++) {
        const float* cp = &g_C[((size_t)(b * V_ + v) * N_ + n) * TO_];
        c1[v] = *(const float4*)&cp[o0];
        c2[v] = *(const float4*)&cp[512 + o0];
    }
#pragma unroll
    for (int j = 0; j < 4; j++) {
        w1[j] = *(const float4*)&g_Wp[j * TO_ + o0];
        w2[j] = *(const float4*)&g_Wp[j * TO_ + 512 + o0];
    }
    float4 a1 = *(const float4*)&att[o0];
    float4 a2 = *(const float4*)&att[512 + o0];

    float red[32];
#pragma unroll
    for (int g = 0; g < 4; g++) {
#pragma unroll
        for (int hv = 0; hv < 4; hv++) {
            const int u = g ^ hv;
            float4 h = c1[hv];
            f4add(h, c2[u]);
#pragma unroll
            for (int j = 0; j < 4; j++) {
                if (flip_jr(j, u))  f4fma(h, -2.f * sx[hv][j], w1[j]);
                if (flip_jr(j, hv)) f4fma(h, -2.f * sx[u][j],  w2[j]);
            }
            float4 lh;
            lh.x = h.x > 0.f ? h.x : 0.2f * h.x;
            lh.y = h.y > 0.f ? h.y : 0.2f * h.y;
            lh.z = h.z > 0.f ? h.z : 0.2f * h.z;
            lh.w = h.w > 0.f ? h.w : 0.2f * h.w;
            red[g * 4 + hv]      = a1.x * lh.x + a1.y * lh.y + a1.z * lh.z + a1.w * lh.w;
            red[16 + g * 4 + hv] = a2.x * lh.x + a2.y * lh.y + a2.z * lh.z + a2.w * lh.w;
        }
    }
#pragma unroll
    for (int o2 = 16; o2; o2 >>= 1)
#pragma unroll
        for (int i = 0; i < 32; i++) red[i] += __shfl_xor_sync(0xffffffffu, red[i], o2);
    __shared__ float sred[4][32];
    int warp = t >> 5, lane = t & 31;
    if (lane == 0) {
#pragma unroll
        for (int i = 0; i < 32; i++) sred[warp][i] = red[i];
    }
    __syncthreads();
    if (t < 32) {
        float v = sred[0][t] + sred[1][t] + sred[2][t] + sred[3][t];
        if (t < 16) g_sa[(size_t)(b * 16 + t) * N_ + n] = v;
        else        g_sb[(size_t)(b * 16 + (t - 16)) * N_ + n] = v;
    }
}

// ---------------- K4: global softmax per (b, pair), smem tables -------------
__global__ __launch_bounds__(512) void k_soft(const int* __restrict__ ei) {
    const int b = blockIdx.x >> 4, p = blockIdx.x & 15;
    __shared__ float s_sa[N_], s_sb[N_];
    __shared__ float red[512];
    const int t = threadIdx.x;
    {
        const float* sa = &g_sa[(size_t)(b * 16 + p) * N_];
        const float* sb = &g_sb[(size_t)(b * 16 + p) * N_];
        for (int i = t; i < N_; i += 512) { s_sa[i] = sa[i]; s_sb[i] = sb[i]; }
    }
    __syncthreads();

    float lm = -1e30f;
    for (int e = t; e < ET_; e += 512) {
        int s = (e < E_) ? ei[e] : e - E_;
        int d = (e < E_) ? ei[E_ + e] : e - E_;
        lm = fmaxf(lm, s_sa[s] + s_sb[d]);
    }
    red[t] = lm;
    __syncthreads();
    for (int o2 = 256; o2; o2 >>= 1) {
        if (t < o2) red[t] = fmaxf(red[t], red[t + o2]);
        __syncthreads();
    }
    const float mx = red[0];
    __syncthreads();

    float ls = 0.f;
    for (int e = t; e < ET_; e += 512) {
        int s = (e < E_) ? ei[e] : e - E_;
        int d = (e < E_) ? ei[E_ + e] : e - E_;
        ls += __expf(s_sa[s] + s_sb[d] - mx);
    }
    red[t] = ls;
    __syncthreads();
    for (int o2 = 256; o2; o2 >>= 1) {
        if (t < o2) red[t] += red[t + o2];
        __syncthreads();
    }
    const float inv = 1.f / red[0];

    for (int e = t; e < ET_; e += 512) {
        int s = (e < E_) ? ei[e] : e - E_;
        int d = (e < E_) ? ei[E_ + e] : e - E_;
        g_w[(size_t)(b * ET_ + e) * 16 + p] = __expf(s_sa[s] + s_sb[d] - mx) * inv;
    }
}

// ---------------- K5: edge gather (fp16 C) + rank-4 corr + epilogue ---------
__global__ __launch_bounds__(128) void k_edge(const float* __restrict__ x,
                                              const float* __restrict__ bias,
                                              float* __restrict__ out) {
    const int n = blockIdx.x, b = blockIdx.y;
    const int t = threadIdx.x;
    const int o0 = t * 4;
    const int beg = g_off[n], end = g_off[n + 1];

    __shared__ int   sh_src[128];
    __shared__ int   sh_eid[128];
    __shared__ float sh_w[128][16];

    float4 acc[4];
#pragma unroll
    for (int g = 0; g < 4; g++) acc[g] = f4z();
    float cr[32];
#pragma unroll
    for (int i = 0; i < 32; i++) cr[i] = 0.f;

    for (int c0 = beg; c0 < end; c0 += 128) {
        const int cnt = min(128, end - c0);
        __syncthreads();
        if (t < cnt) { sh_src[t] = g_srcs[c0 + t]; sh_eid[t] = g_eids[c0 + t]; }
        __syncthreads();
        for (int i = t; i < cnt * 16; i += 128) {
            int e = i >> 4, p = i & 15;
            sh_w[e][p] = g_w[((size_t)b * ET_ + sh_eid[e]) * 16 + p];
        }
        __syncthreads();

        // main accumulation: every thread walks every edge (owns 4 outputs)
        for (int e = 0; e < cnt; e++) {
            const int s = sh_src[e];
            float c1[4][4], c2[4][4];
#pragma unroll
            for (int v = 0; v < 4; v++) {
                const __half* cp = &g_Ch[((size_t)(b * V_ + v) * N_ + s) * TO_];
                uint2 u1 = *(const uint2*)(cp + o0);
                uint2 u2 = *(const uint2*)(cp + 512 + o0);
                float2 p0 = __half22float2(*(__half2*)&u1.x);
                float2 p1 = __half22float2(*(__half2*)&u1.y);
                float2 q0 = __half22float2(*(__half2*)&u2.x);
                float2 q1 = __half22float2(*(__half2*)&u2.y);
                c1[v][0] = p0.x; c1[v][1] = p0.y; c1[v][2] = p1.x; c1[v][3] = p1.y;
                c2[v][0] = q0.x; c2[v][1] = q0.y; c2[v][2] = q1.x; c2[v][3] = q1.y;
            }
#pragma unroll
            for (int g = 0; g < 4; g++) {
#pragma unroll
                for (int v = 0; v < 4; v++) {
                    const float w1 = sh_w[e][g * 4 + v];
                    const float w2 = sh_w[e][g * 4 + (g ^ v)];
                    acc[g].x += w1 * c1[v][0] + w2 * c2[v][0];
                    acc[g].y += w1 * c1[v][1] + w2 * c2[v][1];
                    acc[g].z += w1 * c1[v][2] + w2 * c2[v][2];
                    acc[g].w += w1 * c1[v][3] + w2 * c2[v][3];
                }
            }
        }

        // rank-4 correction scalars (thread-strided over edges)
        for (int e = t; e < cnt; e += 128) {
            const int s = sh_src[e];
            float xb[4][4];
#pragma unroll
            for (int v = 0; v < 4; v++) {
                float4 tv = *(const float4*)&x[((size_t)(b * V_ + v) * N_ + s) * F_];
                xb[v][0] = tv.x; xb[v][1] = tv.y; xb[v][2] = tv.z; xb[v][3] = tv.w;
            }
#pragma unroll
            for (int g = 0; g < 4; g++) {
#pragma unroll
                for (int hv = 0; hv < 4; hv++) {
                    const float wgh = sh_w[e][g * 4 + hv];
                    const int u = g ^ hv;
#pragma unroll
                    for (int j = 0; j < 4; j++) {
                        if (flip_jr(j, u))  cr[g * 8 + j]     += wgh * (-2.f) * xb[hv][j];
                        if (flip_jr(j, hv)) cr[g * 8 + 4 + j] += wgh * (-2.f) * xb[u][j];
                    }
                }
            }
        }
    }

#pragma unroll
    for (int o2 = 16; o2; o2 >>= 1)
#pragma unroll
        for (int i = 0; i < 32; i++) cr[i] += __shfl_xor_sync(0xffffffffu, cr[i], o2);

    __shared__ float sred[4][32];
    __shared__ float fc[32];
    const int warp = t >> 5, lane = t & 31;
    if (lane == 0) {
#pragma unroll
        for (int i = 0; i < 32; i++) sred[warp][i] = cr[i];
    }
    __syncthreads();
    if (t < 32) fc[t] = sred[0][t] + sred[1][t] + sred[2][t] + sred[3][t];
    __syncthreads();

    float4 w1r[4], w2r[4];
#pragma unroll
    for (int j = 0; j < 4; j++) {
        w1r[j] = *(const float4*)&g_Wp[j * TO_ + o0];
        w2r[j] = *(const float4*)&g_Wp[j * TO_ + 512 + o0];
    }
    float4 bb = *(const float4*)&bias[o0];
#pragma unroll
    for (int g = 0; g < 4; g++) {
        float4 r = acc[g];
#pragma unroll
        for (int j = 0; j < 4; j++) {
            f4fma(r, fc[g * 8 + j], w1r[j]);
            f4fma(r, fc[g * 8 + 4 + j], w2r[j]);
        }
        float4 o4;
        o4.x = 0.25f * r.x + bb.x;
        o4.y = 0.25f * r.y + bb.y;
        o4.z = 0.25f * r.z + bb.z;
        o4.w = 0.25f * r.w + bb.w;
        *(float4*)&out[((size_t)(b * V_ + g) * N_ + n) * O_ + o0] = o4;
    }
}

// ---------------- launch ----------------------------------------------------
extern "C" void kernel_launch(void* const* d_in, const int* in_sizes, int n_in,
                              void* d_out, int out_size) {
    const float* x    = (const float*)d_in[0];
    const int*   ei   = (const int*)d_in[1];
    const float* W    = (const float*)d_in[2];
    const float* att  = (const float*)d_in[3];
    const float* bias = (const float*)d_in[4];
    float* out = (float*)d_out;

    k_prep<<<(F_ * TO_ + 255) / 256, 256>>>(W);
    k_gemm<<<dim3(8, 16, 8), 256>>>(x);
    k_count<<<(ET_ + 255) / 256, 256>>>(ei);
    k_scan<<<1, 1024>>>();
    k_fill<<<(ET_ + 255) / 256, 256>>>(ei);
    k_sab<<<dim3(N_, B_), 128>>>(x, att);
    k_soft<<<32, 512>>>(ei);
    k_edge<<<dim3(N_, B_), 128>>>(x, bias, out);
}

// round 3
// speedup vs baseline: 1.0996x; 1.0690x over previous
#include <cuda_runtime.h>
#include <cuda_fp16.h>
#include <cstdint>

// Problem constants (fixed by setup_inputs)
#define B_  2
#define V_  4
#define N_  2048
#define F_  128
#define E_  32768
#define ET_ (E_ + N_)      // 34816 edges incl self-loops
#define O_  512
#define TO_ 1024           // C row = [C1 | C2]

// ---------------- scratch (device globals; no runtime alloc) ----------------
__device__ __half g_Ch[B_ * V_ * N_ * TO_]; // 32 MB fp16 C tables
__device__ float  g_Wp[F_ * TO_];           // packed [W1 | W2] (128 x 1024)
__device__ float  g_sa[B_ * 16 * N_];
__device__ float  g_sb[B_ * 16 * N_];
__device__ float  g_w [B_ * ET_ * 16];      // softmax weights [b][edge][pair]
__device__ int    g_cnt[N_];
__device__ int    g_off[N_ + 1];
__device__ int    g_fill[N_];
__device__ int    g_srcs[ET_];
__device__ int    g_eids[ET_];

// sign-flip predicate: features {0,2} flip when r&1, {1,3} flip when r&2
__device__ __forceinline__ bool flip_jr(int j, int r) {
    return ((j & 1) == 0) ? ((r & 1) != 0) : ((r & 2) != 0);
}
__device__ __forceinline__ float4 f4z() { return make_float4(0.f, 0.f, 0.f, 0.f); }
__device__ __forceinline__ void f4fma(float4& acc, float s, const float4& a) {
    acc.x += s * a.x; acc.y += s * a.y; acc.z += s * a.z; acc.w += s * a.w;
}
__device__ __forceinline__ void f4add(float4& acc, const float4& a) {
    acc.x += a.x; acc.y += a.y; acc.z += a.z; acc.w += a.w;
}
// unpack 4 fp16 (uint2) -> float4
__device__ __forceinline__ float4 h4f(uint2 u) {
    float2 a = __half22float2(*(__half2*)&u.x);
    float2 b = __half22float2(*(__half2*)&u.y);
    return make_float4(a.x, a.y, b.x, b.y);
}

// ---------------- K0: pack W + zero counters --------------------------------
__global__ void k_prep(const float* __restrict__ W) {
    int i = blockIdx.x * blockDim.x + threadIdx.x;
    if (i < N_) g_cnt[i] = 0;
    if (i >= F_ * TO_) return;
    int k = i / TO_, j = i % TO_;
    g_Wp[i] = (j < O_) ? W[k * O_ + j] : W[(F_ + k) * O_ + (j - O_)];
}

// ---------------- CSR build --------------------------------------------------
__global__ void k_count(const int* __restrict__ ei) {
    int e = blockIdx.x * blockDim.x + threadIdx.x;
    if (e >= ET_) return;
    int d = (e < E_) ? ei[E_ + e] : e - E_;
    atomicAdd(&g_cnt[d], 1);
}
__global__ __launch_bounds__(1024) void k_scan() {
    __shared__ int sh[N_];
    int t = threadIdx.x;
    sh[t] = g_cnt[t];
    sh[t + 1024] = g_cnt[t + 1024];
    __syncthreads();
    for (int d = 1; d < N_; d <<= 1) {
        int i0 = t, i1 = t + 1024;
        int v0 = (i0 >= d) ? sh[i0 - d] : 0;
        int v1 = (i1 >= d) ? sh[i1 - d] : 0;
        __syncthreads();
        sh[i0] += v0;
        sh[i1] += v1;
        __syncthreads();
    }
    g_off[t + 1] = sh[t];
    g_off[t + 1025] = sh[t + 1024];
    g_fill[t] = (t == 0) ? 0 : sh[t - 1];
    g_fill[t + 1024] = sh[t + 1023];
    if (t == 0) g_off[0] = 0;
}
__global__ void k_fill(const int* __restrict__ ei) {
    int e = blockIdx.x * blockDim.x + threadIdx.x;
    if (e >= ET_) return;
    int s = (e < E_) ? ei[e] : e - E_;
    int d = (e < E_) ? ei[E_ + e] : e - E_;
    int slot = atomicAdd(&g_fill[d], 1);
    g_srcs[slot] = s;
    g_eids[slot] = e;
}

// ---------------- K1: C[bv] = x[bv](2048x128) @ Wp(128x1024), fp16 out ------
// BM=128, BN=128, BK=16, 256 threads, 8x8 microtile, reg-staged double buffer.
__global__ __launch_bounds__(256) void k_gemm(const float* __restrict__ x) {
    __shared__ float As[2][16][132];   // [k][m], padded
    __shared__ float Bs[2][16][128];   // [k][n]
    const int bv = blockIdx.z;
    const int m0 = blockIdx.y * 128;
    const int n0 = blockIdx.x * 128;
    const int t  = threadIdx.x;
    const int tm = t >> 4;       // 0..15
    const int tn = t & 15;       // 0..15

    const float* xA = x + ((size_t)bv * N_ + m0) * F_;

    const int fA0 = t * 2,     mA0 = fA0 >> 2, kqA0 = (fA0 & 3) * 4;
    const int fA1 = t * 2 + 1, mA1 = fA1 >> 2, kqA1 = (fA1 & 3) * 4;
    const int kB0 = t >> 5,    nqB = (t & 31) * 4;
    const int kB1 = kB0 + 8;

    float4 ra0, ra1, rb0, rb1;

    ra0 = *(const float4*)&xA[mA0 * F_ + kqA0];
    ra1 = *(const float4*)&xA[mA1 * F_ + kqA1];
    rb0 = *(const float4*)&g_Wp[kB0 * TO_ + n0 + nqB];
    rb1 = *(const float4*)&g_Wp[kB1 * TO_ + n0 + nqB];
    As[0][kqA0 + 0][mA0] = ra0.x; As[0][kqA0 + 1][mA0] = ra0.y;
    As[0][kqA0 + 2][mA0] = ra0.z; As[0][kqA0 + 3][mA0] = ra0.w;
    As[0][kqA1 + 0][mA1] = ra1.x; As[0][kqA1 + 1][mA1] = ra1.y;
    As[0][kqA1 + 2][mA1] = ra1.z; As[0][kqA1 + 3][mA1] = ra1.w;
    *(float4*)&Bs[0][kB0][nqB] = rb0;
    *(float4*)&Bs[0][kB1][nqB] = rb1;
    __syncthreads();

    float acc[8][8];
#pragma unroll
    for (int i = 0; i < 8; i++)
#pragma unroll
        for (int j = 0; j < 8; j++) acc[i][j] = 0.f;

    int buf = 0;
    for (int kc = 0; kc < 8; kc++) {
        if (kc < 7) {
            const int k16 = (kc + 1) * 16;
            ra0 = *(const float4*)&xA[mA0 * F_ + k16 + kqA0];
            ra1 = *(const float4*)&xA[mA1 * F_ + k16 + kqA1];
            rb0 = *(const float4*)&g_Wp[(k16 + kB0) * TO_ + n0 + nqB];
            rb1 = *(const float4*)&g_Wp[(k16 + kB1) * TO_ + n0 + nqB];
        }
#pragma unroll
        for (int kk = 0; kk < 16; kk++) {
            float4 aA = *(const float4*)&As[buf][kk][tm * 8];
            float4 aB = *(const float4*)&As[buf][kk][tm * 8 + 4];
            float4 bA = *(const float4*)&Bs[buf][kk][tn * 4];
            float4 bB = *(const float4*)&Bs[buf][kk][64 + tn * 4];
            float a[8] = {aA.x, aA.y, aA.z, aA.w, aB.x, aB.y, aB.z, aB.w};
            float bb[8] = {bA.x, bA.y, bA.z, bA.w, bB.x, bB.y, bB.z, bB.w};
#pragma unroll
            for (int i = 0; i < 8; i++)
#pragma unroll
                for (int j = 0; j < 8; j++)
                    acc[i][j] += a[i] * bb[j];
        }
        if (kc < 7) {
            const int nb = buf ^ 1;
            As[nb][kqA0 + 0][mA0] = ra0.x; As[nb][kqA0 + 1][mA0] = ra0.y;
            As[nb][kqA0 + 2][mA0] = ra0.z; As[nb][kqA0 + 3][mA0] = ra0.w;
            As[nb][kqA1 + 0][mA1] = ra1.x; As[nb][kqA1 + 1][mA1] = ra1.y;
            As[nb][kqA1 + 2][mA1] = ra1.z; As[nb][kqA1 + 3][mA1] = ra1.w;
            *(float4*)&Bs[nb][kB0][nqB] = rb0;
            *(float4*)&Bs[nb][kB1][nqB] = rb1;
        }
        __syncthreads();
        buf ^= 1;
    }

#pragma unroll
    for (int i = 0; i < 8; i++) {
        const int row = m0 + tm * 8 + i;
        __half* Hp = &g_Ch[((size_t)bv * N_ + row) * TO_];
        const int c0 = n0 + tn * 4, c1 = n0 + 64 + tn * 4;
        __half2 h0 = __floats2half2_rn(acc[i][0], acc[i][1]);
        __half2 h1 = __floats2half2_rn(acc[i][2], acc[i][3]);
        __half2 h2 = __floats2half2_rn(acc[i][4], acc[i][5]);
        __half2 h3 = __floats2half2_rn(acc[i][6], acc[i][7]);
        uint2 u0, u1;
        u0.x = *(const unsigned*)&h0; u0.y = *(const unsigned*)&h1;
        u1.x = *(const unsigned*)&h2; u1.y = *(const unsigned*)&h3;
        *(uint2*)&Hp[c0] = u0;
        *(uint2*)&Hp[c1] = u1;
    }
}

// ---------------- K3: salpha/sbeta per (b, n, 16 pairs) ---------------------
__global__ __launch_bounds__(128) void k_sab(const float* __restrict__ x,
                                             const float* __restrict__ att) {
    const int n = blockIdx.x, b = blockIdx.y;
    const int t = threadIdx.x;
    const int o0 = t * 4;

    __shared__ float sx[V_][4];
    if (t < 16) sx[t >> 2][t & 3] = x[((size_t)(b * V_ + (t >> 2)) * N_ + n) * F_ + (t & 3)];
    __syncthreads();

    float4 c1[4], c2[4], w1[4], w2[4];
#pragma unroll
    for (int v = 0; v < 4; v++) {
        const __half* cp = &g_Ch[((size_t)(b * V_ + v) * N_ + n) * TO_];
        c1[v] = h4f(*(const uint2*)(cp + o0));
        c2[v] = h4f(*(const uint2*)(cp + 512 + o0));
    }
#pragma unroll
    for (int j = 0; j < 4; j++) {
        w1[j] = *(const float4*)&g_Wp[j * TO_ + o0];
        w2[j] = *(const float4*)&g_Wp[j * TO_ + 512 + o0];
    }
    float4 a1 = *(const float4*)&att[o0];
    float4 a2 = *(const float4*)&att[512 + o0];

    float red[32];
#pragma unroll
    for (int g = 0; g < 4; g++) {
#pragma unroll
        for (int hv = 0; hv < 4; hv++) {
            const int u = g ^ hv;
            float4 h = c1[hv];
            f4add(h, c2[u]);
#pragma unroll
            for (int j = 0; j < 4; j++) {
                if (flip_jr(j, u))  f4fma(h, -2.f * sx[hv][j], w1[j]);
                if (flip_jr(j, hv)) f4fma(h, -2.f * sx[u][j],  w2[j]);
            }
            float4 lh;
            lh.x = h.x > 0.f ? h.x : 0.2f * h.x;
            lh.y = h.y > 0.f ? h.y : 0.2f * h.y;
            lh.z = h.z > 0.f ? h.z : 0.2f * h.z;
            lh.w = h.w > 0.f ? h.w : 0.2f * h.w;
            red[g * 4 + hv]      = a1.x * lh.x + a1.y * lh.y + a1.z * lh.z + a1.w * lh.w;
            red[16 + g * 4 + hv] = a2.x * lh.x + a2.y * lh.y + a2.z * lh.z + a2.w * lh.w;
        }
    }
#pragma unroll
    for (int o2 = 16; o2; o2 >>= 1)
#pragma unroll
        for (int i = 0; i < 32; i++) red[i] += __shfl_xor_sync(0xffffffffu, red[i], o2);
    __shared__ float sred[4][32];
    int warp = t >> 5, lane = t & 31;
    if (lane == 0) {
#pragma unroll
        for (int i = 0; i < 32; i++) sred[warp][i] = red[i];
    }
    __syncthreads();
    if (t < 32) {
        float v = sred[0][t] + sred[1][t] + sred[2][t] + sred[3][t];
        if (t < 16) g_sa[(size_t)(b * 16 + t) * N_ + n] = v;
        else        g_sb[(size_t)(b * 16 + (t - 16)) * N_ + n] = v;
    }
}

// ---------------- K4: global softmax per (b, pair), smem tables -------------
__global__ __launch_bounds__(1024) void k_soft(const int* __restrict__ ei) {
    const int b = blockIdx.x >> 4, p = blockIdx.x & 15;
    __shared__ float s_sa[N_], s_sb[N_];
    __shared__ float red[1024];
    const int t = threadIdx.x;
    {
        const float* sa = &g_sa[(size_t)(b * 16 + p) * N_];
        const float* sb = &g_sb[(size_t)(b * 16 + p) * N_];
        for (int i = t; i < N_; i += 1024) { s_sa[i] = sa[i]; s_sb[i] = sb[i]; }
    }
    __syncthreads();

    float lm = -1e30f;
    for (int e = t; e < ET_; e += 1024) {
        int s = (e < E_) ? ei[e] : e - E_;
        int d = (e < E_) ? ei[E_ + e] : e - E_;
        lm = fmaxf(lm, s_sa[s] + s_sb[d]);
    }
    red[t] = lm;
    __syncthreads();
    for (int o2 = 512; o2; o2 >>= 1) {
        if (t < o2) red[t] = fmaxf(red[t], red[t + o2]);
        __syncthreads();
    }
    const float mx = red[0];
    __syncthreads();

    float ls = 0.f;
    for (int e = t; e < ET_; e += 1024) {
        int s = (e < E_) ? ei[e] : e - E_;
        int d = (e < E_) ? ei[E_ + e] : e - E_;
        ls += __expf(s_sa[s] + s_sb[d] - mx);
    }
    red[t] = ls;
    __syncthreads();
    for (int o2 = 512; o2; o2 >>= 1) {
        if (t < o2) red[t] += red[t + o2];
        __syncthreads();
    }
    const float inv = 1.f / red[0];

    for (int e = t; e < ET_; e += 1024) {
        int s = (e < E_) ? ei[e] : e - E_;
        int d = (e < E_) ? ei[E_ + e] : e - E_;
        g_w[(size_t)(b * ET_ + e) * 16 + p] = __expf(s_sa[s] + s_sb[d] - mx) * inv;
    }
}

// ---------------- K5: edge gather (fp16 C, pipelined) + epilogue ------------
__global__ __launch_bounds__(128) void k_edge(const float* __restrict__ x,
                                              const float* __restrict__ bias,
                                              float* __restrict__ out) {
    const int n = blockIdx.x, b = blockIdx.y;
    const int t = threadIdx.x;
    const int o0 = t * 4;
    const int beg = g_off[n], end = g_off[n + 1];

    __shared__ int   sh_src[128];
    __shared__ int   sh_eid[128];
    __shared__ float sh_w[128][16];

    float4 acc[4];
#pragma unroll
    for (int g = 0; g < 4; g++) acc[g] = f4z();
    float cr[32];
#pragma unroll
    for (int i = 0; i < 32; i++) cr[i] = 0.f;

    for (int c0 = beg; c0 < end; c0 += 128) {
        const int cnt = min(128, end - c0);
        __syncthreads();
        if (t < cnt) { sh_src[t] = g_srcs[c0 + t]; sh_eid[t] = g_eids[c0 + t]; }
        __syncthreads();
        for (int i = t; i < cnt * 16; i += 128) {
            int e = i >> 4, p = i & 15;
            sh_w[e][p] = g_w[((size_t)b * ET_ + sh_eid[e]) * 16 + p];
        }
        __syncthreads();

        // software-pipelined edge walk: load e+1 while computing e
        uint2 cu1[4], cu2[4], nu1[4], nu2[4];
        {
            const int s = sh_src[0];
#pragma unroll
            for (int v = 0; v < 4; v++) {
                const __half* cp = &g_Ch[((size_t)(b * V_ + v) * N_ + s) * TO_];
                cu1[v] = *(const uint2*)(cp + o0);
                cu2[v] = *(const uint2*)(cp + 512 + o0);
            }
        }
        for (int e = 0; e < cnt; e++) {
            if (e + 1 < cnt) {
                const int s = sh_src[e + 1];
#pragma unroll
                for (int v = 0; v < 4; v++) {
                    const __half* cp = &g_Ch[((size_t)(b * V_ + v) * N_ + s) * TO_];
                    nu1[v] = *(const uint2*)(cp + o0);
                    nu2[v] = *(const uint2*)(cp + 512 + o0);
                }
            }
            float4 c1[4], c2[4];
#pragma unroll
            for (int v = 0; v < 4; v++) { c1[v] = h4f(cu1[v]); c2[v] = h4f(cu2[v]); }
#pragma unroll
            for (int g = 0; g < 4; g++) {
#pragma unroll
                for (int v = 0; v < 4; v++) {
                    const float w1 = sh_w[e][g * 4 + v];
                    const float w2 = sh_w[e][g * 4 + (g ^ v)];
                    acc[g].x += w1 * c1[v].x + w2 * c2[v].x;
                    acc[g].y += w1 * c1[v].y + w2 * c2[v].y;
                    acc[g].z += w1 * c1[v].z + w2 * c2[v].z;
                    acc[g].w += w1 * c1[v].w + w2 * c2[v].w;
                }
            }
#pragma unroll
            for (int v = 0; v < 4; v++) { cu1[v] = nu1[v]; cu2[v] = nu2[v]; }
        }

        // rank-4 correction scalars (thread-strided over edges)
        for (int e = t; e < cnt; e += 128) {
            const int s = sh_src[e];
            float xb[4][4];
#pragma unroll
            for (int v = 0; v < 4; v++) {
                float4 tv = *(const float4*)&x[((size_t)(b * V_ + v) * N_ + s) * F_];
                xb[v][0] = tv.x; xb[v][1] = tv.y; xb[v][2] = tv.z; xb[v][3] = tv.w;
            }
#pragma unroll
            for (int g = 0; g < 4; g++) {
#pragma unroll
                for (int hv = 0; hv < 4; hv++) {
                    const float wgh = sh_w[e][g * 4 + hv];
                    const int u = g ^ hv;
#pragma unroll
                    for (int j = 0; j < 4; j++) {
                        if (flip_jr(j, u))  cr[g * 8 + j]     += wgh * (-2.f) * xb[hv][j];
                        if (flip_jr(j, hv)) cr[g * 8 + 4 + j] += wgh * (-2.f) * xb[u][j];
                    }
                }
            }
        }
    }

#pragma unroll
    for (int o2 = 16; o2; o2 >>= 1)
#pragma unroll
        for (int i = 0; i < 32; i++) cr[i] += __shfl_xor_sync(0xffffffffu, cr[i], o2);

    __shared__ float sred[4][32];
    __shared__ float fc[32];
    const int warp = t >> 5, lane = t & 31;
    if (lane == 0) {
#pragma unroll
        for (int i = 0; i < 32; i++) sred[warp][i] = cr[i];
    }
    __syncthreads();
    if (t < 32) fc[t] = sred[0][t] + sred[1][t] + sred[2][t] + sred[3][t];
    __syncthreads();

    float4 w1r[4], w2r[4];
#pragma unroll
    for (int j = 0; j < 4; j++) {
        w1r[j] = *(const float4*)&g_Wp[j * TO_ + o0];
        w2r[j] = *(const float4*)&g_Wp[j * TO_ + 512 + o0];
    }
    float4 bb = *(const float4*)&bias[o0];
#pragma unroll
    for (int g = 0; g < 4; g++) {
        float4 r = acc[g];
#pragma unroll
        for (int j = 0; j < 4; j++) {
            f4fma(r, fc[g * 8 + j], w1r[j]);
            f4fma(r, fc[g * 8 + 4 + j], w2r[j]);
        }
        float4 o4;
        o4.x = 0.25f * r.x + bb.x;
        o4.y = 0.25f * r.y + bb.y;
        o4.z = 0.25f * r.z + bb.z;
        o4.w = 0.25f * r.w + bb.w;
        *(float4*)&out[((size_t)(b * V_ + g) * N_ + n) * O_ + o0] = o4;
    }
}

// ---------------- launch ----------------------------------------------------
extern "C" void kernel_launch(void* const* d_in, const int* in_sizes, int n_in,
                              void* d_out, int out_size) {
    const float* x    = (const float*)d_in[0];
    const int*   ei   = (const int*)d_in[1];
    const float* W    = (const float*)d_in[2];
    const float* att  = (const float*)d_in[3];
    const float* bias = (const float*)d_in[4];
    float* out = (float*)d_out;

    // k_gemm deliberately in launch slot 4 (ncu capture window)
    k_prep<<<(F_ * TO_ + 255) / 256, 256>>>(W);
    k_count<<<(ET_ + 255) / 256, 256>>>(ei);
    k_scan<<<1, 1024>>>();
    k_gemm<<<dim3(8, 16, 8), 256>>>(x);
    k_fill<<<(ET_ + 255) / 256, 256>>>(ei);
    k_sab<<<dim3(N_, B_), 128>>>(x, att);
    k_soft<<<32, 1024>>>(ei);
    k_edge<<<dim3(N_, B_), 128>>>(x, bias, out);
}